// round 9
// baseline (speedup 1.0000x reference)
#include <cuda_runtime.h>
#include <cuda_bf16.h>
#include <cuda.h>
#include <cstdint>

// ---------------- problem constants ----------------
#define S_LEN 4096
#define NROWS 8192
#define D_IN  7168
#define LORA  1536
#define NH    64
#define DHD   128
#define QN    (NROWS * NH * DHD)
#define WN    (NROWS * NH)
#define KN    (NROWS * DHD)

#define WSCALE 0.011048543456039806f  // (H*DH)^-0.5
#define HSCALE 0.08838834764831845f   // 128^-0.5

// ---------------- device scratch (bf16 hi/lo splits) ----------------
__device__ __nv_bfloat16 g_qr_h[NROWS * LORA];
__device__ __nv_bfloat16 g_qr_l[NROWS * LORA];
__device__ __nv_bfloat16 g_wq_h[NROWS * LORA];
__device__ __nv_bfloat16 g_wq_l[NROWS * LORA];
__device__ __nv_bfloat16 g_x_h[(size_t)NROWS * D_IN];
__device__ __nv_bfloat16 g_x_l[(size_t)NROWS * D_IN];
__device__ __nv_bfloat16 g_wb_h[256 * D_IN];
__device__ __nv_bfloat16 g_wb_l[256 * D_IN];

// ---------------- split helpers ----------------
__device__ __forceinline__ uint32_t pack_bf2(__nv_bfloat16 a, __nv_bfloat16 b) {
    return (uint32_t)__bfloat16_as_ushort(a) | ((uint32_t)__bfloat16_as_ushort(b) << 16);
}
__device__ __forceinline__ void split4(float4 v, uint2& hi, uint2& lo) {
    __nv_bfloat16 hx = __float2bfloat16_rn(v.x);
    __nv_bfloat16 hy = __float2bfloat16_rn(v.y);
    __nv_bfloat16 hz = __float2bfloat16_rn(v.z);
    __nv_bfloat16 hw = __float2bfloat16_rn(v.w);
    __nv_bfloat16 lx = __float2bfloat16_rn(v.x - __bfloat162float(hx));
    __nv_bfloat16 ly = __float2bfloat16_rn(v.y - __bfloat162float(hy));
    __nv_bfloat16 lz = __float2bfloat16_rn(v.z - __bfloat162float(hz));
    __nv_bfloat16 lw = __float2bfloat16_rn(v.w - __bfloat162float(hw));
    hi = make_uint2(pack_bf2(hx, hy), pack_bf2(hz, hw));
    lo = make_uint2(pack_bf2(lx, ly), pack_bf2(lz, lw));
}

#define N4Q (NROWS * LORA / 4)
#define N4X (NROWS * D_IN / 4)
#define N4B (256 * D_IN / 4)
#define PREPQ_TOTAL (2 * N4Q + N4B)

// chain 1 prep: qr + wqb splits + combined proj-weight build (small)
__global__ void prep_q(const float4* __restrict__ qr, const float4* __restrict__ wqb,
                       const float* __restrict__ wk, const float* __restrict__ wp)
{
    int i = blockIdx.x * blockDim.x + threadIdx.x;
    if (i >= PREPQ_TOTAL) return;
    if (i < N4Q) {
        uint2 h, l; split4(qr[i], h, l);
        ((uint2*)g_qr_h)[i] = h; ((uint2*)g_qr_l)[i] = l;
    } else if (i < 2 * N4Q) {
        int j = i - N4Q;
        uint2 h, l; split4(wqb[j], h, l);
        ((uint2*)g_wq_h)[j] = h; ((uint2*)g_wq_l)[j] = l;
    } else {
        int j = i - 2 * N4Q;
        int row = j / (D_IN / 4);
        int c4  = j % (D_IN / 4);
        float4 v;
        if (row < 128)      v = ((const float4*)wk)[row * (D_IN / 4) + c4];
        else if (row < 192) {
            v = ((const float4*)wp)[(row - 128) * (D_IN / 4) + c4];
            v.x *= WSCALE; v.y *= WSCALE; v.z *= WSCALE; v.w *= WSCALE;
        } else v = make_float4(0.f, 0.f, 0.f, 0.f);
        uint2 h, l; split4(v, h, l);
        ((uint2*)g_wb_h)[j] = h; ((uint2*)g_wb_l)[j] = l;
    }
}

// chain 2 prep: x splits (big; overlaps gemm_q)
__global__ void prep_x(const float4* __restrict__ x)
{
    int i = blockIdx.x * blockDim.x + threadIdx.x;
    if (i >= N4X) return;
    uint2 h, l; split4(x[i], h, l);
    ((uint2*)g_x_h)[i] = h; ((uint2*)g_x_l)[i] = l;
}

// ---------------- PTX helpers ----------------
__device__ __forceinline__ uint32_t elect_one_pred() {
    uint32_t p;
    asm volatile("{\n\t.reg .pred p;\n\telect.sync _|p, 0xFFFFFFFF;\n\tselp.b32 %0, 1, 0, p;\n\t}" : "=r"(p));
    return p;
}
__device__ __forceinline__ uint32_t smem_u32(const void* p) {
    uint32_t a;
    asm("{ .reg .u64 t; cvta.to.shared.u64 t, %1; cvt.u32.u64 %0, t; }" : "=r"(a) : "l"(p));
    return a;
}

#define MBARRIER_INIT(a, c) \
    asm volatile("mbarrier.init.shared.b64 [%0], %1;" :: "r"((uint32_t)(a)), "r"((uint32_t)(c)) : "memory")
#define MBARRIER_EXPECT_TX(a, b) \
    asm volatile("mbarrier.arrive.expect_tx.shared.b64 _, [%0], %1;" :: "r"((uint32_t)(a)), "r"((uint32_t)(b)) : "memory")
#define MBARRIER_ARRIVE(a) \
    asm volatile("mbarrier.arrive.shared.b64 _, [%0];" :: "r"((uint32_t)(a)) : "memory")

#define MBARRIER_WAIT_PARITY(mbar, par) do {                                          \
    uint32_t _m = (uint32_t)(mbar), _p = (uint32_t)(par), _d;                         \
    asm volatile("{\n\t.reg .pred p;\n\t"                                             \
        "mbarrier.try_wait.parity.acquire.cta.shared::cta.b64 p, [%1], %2;\n\t"       \
        "selp.b32 %0, 1, 0, p;\n\t}" : "=r"(_d) : "r"(_m), "r"(_p) : "memory");       \
    if (!_d) {                                                                         \
        asm volatile("{\n\t.reg .pred P1;\n\t"                                        \
            "WL_%=:\n\t"                                                              \
            "mbarrier.try_wait.parity.acquire.cta.shared::cta.b64 P1, [%0], %1, 0x989680;\n\t" \
            "@P1 bra.uni WD_%=;\n\t"                                                  \
            "bra.uni WL_%=;\n\t"                                                      \
            "WD_%=:\n\t}" :: "r"(_m), "r"(_p) : "memory");                            \
    }                                                                                  \
} while (0)

#define MBARRIER_WAIT_PARITY_RELAXED(mbar, par) do {                                  \
    uint32_t _m = (uint32_t)(mbar), _p = (uint32_t)(par), _d;                         \
    asm volatile("{\n\t.reg .pred p;\n\t"                                             \
        "mbarrier.try_wait.parity.relaxed.cta.shared::cta.b64 p, [%1], %2, 0x989680;\n\t" \
        "selp.b32 %0, 1, 0, p;\n\t}" : "=r"(_d) : "r"(_m), "r"(_p) : "memory");       \
    if (!_d) {                                                                         \
        asm volatile("{\n\t.reg .pred P1;\n\t"                                        \
            "WL_%=:\n\t"                                                              \
            "mbarrier.try_wait.parity.relaxed.cta.shared::cta.b64 P1, [%0], %1, 0x989680;\n\t" \
            "@P1 bra.uni WD_%=;\n\t"                                                  \
            "bra.uni WL_%=;\n\t"                                                      \
            "WD_%=:\n\t}" :: "r"(_m), "r"(_p) : "memory");                            \
    }                                                                                  \
} while (0)

#define TMA_LOAD_3D(sa, tm, cx, cy, cz, mb)                                           \
    asm volatile("cp.async.bulk.tensor.3d.shared::cta.global.tile.mbarrier::complete_tx::bytes " \
        "[%0], [%1, {%2, %3, %4}], [%5];"                                             \
        :: "r"((uint32_t)(sa)), "l"(tm), "r"((int)(cx)), "r"((int)(cy)), "r"((int)(cz)), \
           "r"((uint32_t)(mb)) : "memory")

#define FENCE_PROXY_ASYNC() asm volatile("fence.proxy.async.shared::cta;" ::: "memory")

#define LDSM4(r0, r1, r2, r3, addr)                                              \
    asm volatile("ldmatrix.sync.aligned.m8n8.x4.shared.b16 {%0,%1,%2,%3},[%4];"  \
                 : "=r"(r0), "=r"(r1), "=r"(r2), "=r"(r3) : "r"(addr))

#define MMA_BF16(d, a, b)                                                        \
    asm volatile("mma.sync.aligned.m16n8k16.row.col.f32.bf16.bf16.f32 "          \
                 "{%0,%1,%2,%3},{%4,%5,%6,%7},{%8,%9},{%0,%1,%2,%3};"            \
                 : "+f"((d)[0]), "+f"((d)[1]), "+f"((d)[2]), "+f"((d)[3])        \
                 : "r"((a)[0]), "r"((a)[1]), "r"((a)[2]), "r"((a)[3]),           \
                   "r"((b)[0]), "r"((b)[1]))

// SW128 swizzle: XOR bits [9:7] into bits [6:4] (128B rows)
__device__ __forceinline__ uint32_t swz(uint32_t o) { return o ^ ((o >> 3) & 0x70); }

// ---------------- smem layout ----------------
#define CTRL     1024
#define STAGE_B  98304
#define AH_O     0
#define AL_O     16384
#define BH_O     32768
#define BL_O     65536
#define NSTAGE   2
#define SMEM_TOT (CTRL + NSTAGE * STAGE_B)   // 197632 -> 1 CTA/SM

// =====================================================================
// TMA-fed mma.sync GEMM, tile 128x256, fused epilogues.
// PROJ=true : 64 blocks, K=7168, A=x splits, B=wb; LN+RoPE+FWHT->kout, wout.
// PROJ=false: 2048 blocks, K=1536, A=qr, B=wq; RoPE+FWHT->qout.
// =====================================================================
template<bool PROJ>
__global__ __launch_bounds__(256, 1)
void fused_gemm(const __grid_constant__ CUtensorMap mAh, const __grid_constant__ CUtensorMap mAl,
                const __grid_constant__ CUtensorMap mBh, const __grid_constant__ CUtensorMap mBl,
                float* __restrict__ qout, float* __restrict__ kout, float* __restrict__ wout,
                const float* __restrict__ fc, const float* __restrict__ fs,
                const float* __restrict__ kg, const float* __restrict__ kb)
{
    extern __shared__ char smem_raw[];
    const uint32_t sb = smem_u32(smem_raw);
    const int tid = threadIdx.x, lane = tid & 31, warp = tid >> 5;
    const int wm = warp >> 2, wn = warp & 3;
    const int tm = wm << 6, tn = wn << 6;     // warp tile 64x64

    const int bid = blockIdx.x;
    int bm, bn;
    if (PROJ) { bm = bid; bn = 0; }
    else      { bm = bid & 63; bn = bid >> 6; }
    constexpr int K = PROJ ? D_IN : LORA;
    constexpr int niter = K >> 6;

    if (tid == 0) {
        MBARRIER_INIT(sb + 0, 1);
        MBARRIER_INIT(sb + 8, 1);
        MBARRIER_INIT(sb + 16, 8);
        MBARRIER_INIT(sb + 24, 8);
        FENCE_PROXY_ASYNC();
    }
    __syncthreads();

    const bool producer = (warp == 0) && elect_one_pred();
    const bool wleader  = elect_one_pred();

    if (producer) {
        #pragma unroll
        for (int p = 0; p < NSTAGE; ++p) {
            const uint32_t fb = sb + p * 8;
            MBARRIER_EXPECT_TX(fb, STAGE_B);
            const uint32_t tb = sb + CTRL + p * STAGE_B;
            const int kt = p << 6;
            TMA_LOAD_3D(tb + AH_O, &mAh, kt, bm * 128, 0, fb);
            TMA_LOAD_3D(tb + AL_O, &mAl, kt, bm * 128, 0, fb);
            TMA_LOAD_3D(tb + BH_O, &mBh, kt, bn * 256, 0, fb);
            TMA_LOAD_3D(tb + BL_O, &mBl, kt, bn * 256, 0, fb);
        }
    }

    float acc[4][8][4] = {};
    int fph[NSTAGE] = {0, 0};
    int eph[NSTAGE] = {0, 0};

    int s = 0;
    for (int it = 0; it < niter; ++it) {
        MBARRIER_WAIT_PARITY(sb + s * 8, fph[s]);
        fph[s] ^= 1;
        const uint32_t tb = sb + CTRL + s * STAGE_B;

        #pragma unroll
        for (int s2 = 0; s2 < 4; ++s2) {
            const uint32_t kbyte = s2 << 5;
            uint32_t bhf[8][2], blf[8][2];
            {
                const int g = lane >> 3;
                #pragma unroll
                for (int p = 0; p < 4; ++p) {
                    const int row = tn + (((p << 1) + (g >> 1)) << 3) + (lane & 7);
                    const uint32_t off = swz(row * 128 + kbyte + ((g & 1) << 4));
                    LDSM4(bhf[2*p][0], bhf[2*p][1], bhf[2*p+1][0], bhf[2*p+1][1], tb + BH_O + off);
                    LDSM4(blf[2*p][0], blf[2*p][1], blf[2*p+1][0], blf[2*p+1][1], tb + BL_O + off);
                }
            }
            uint32_t a[4][4];
            #pragma unroll
            for (int i = 0; i < 4; ++i) {
                const int row = tm + (i << 4) + (lane & 15);
                const uint32_t off = swz(row * 128 + kbyte + ((lane >> 4) << 4));
                LDSM4(a[i][0], a[i][1], a[i][2], a[i][3], tb + AH_O + off);
            }
            #pragma unroll
            for (int i = 0; i < 4; ++i)
                #pragma unroll
                for (int j = 0; j < 8; ++j) {
                    MMA_BF16(acc[i][j], a[i], bhf[j]);
                    MMA_BF16(acc[i][j], a[i], blf[j]);
                }
            #pragma unroll
            for (int i = 0; i < 4; ++i) {
                const int row = tm + (i << 4) + (lane & 15);
                const uint32_t off = swz(row * 128 + kbyte + ((lane >> 4) << 4));
                LDSM4(a[i][0], a[i][1], a[i][2], a[i][3], tb + AL_O + off);
            }
            #pragma unroll
            for (int i = 0; i < 4; ++i)
                #pragma unroll
                for (int j = 0; j < 8; ++j)
                    MMA_BF16(acc[i][j], a[i], bhf[j]);
        }

        if (wleader) MBARRIER_ARRIVE(sb + 16 + s * 8);

        if (producer && it + NSTAGE < niter) {
            MBARRIER_WAIT_PARITY_RELAXED(sb + 16 + s * 8, eph[s]);
            eph[s] ^= 1;
            const uint32_t fb = sb + s * 8;
            MBARRIER_EXPECT_TX(fb, STAGE_B);
            const int kt = (it + NSTAGE) << 6;
            TMA_LOAD_3D(tb + AH_O, &mAh, kt, bm * 128, 0, fb);
            TMA_LOAD_3D(tb + AL_O, &mAl, kt, bm * 128, 0, fb);
            TMA_LOAD_3D(tb + BH_O, &mBh, kt, bn * 256, 0, fb);
            TMA_LOAD_3D(tb + BL_O, &mBl, kt, bn * 256, 0, fb);
        }
        if (++s == NSTAGE) s = 0;
    }

    // ================= fused epilogue =================
    __syncthreads();
    float* tile = reinterpret_cast<float*>(smem_raw + CTRL);   // [128][264]
    #pragma unroll
    for (int i = 0; i < 4; ++i)
        #pragma unroll
        for (int j = 0; j < 8; ++j) {
            const int r0 = tm + (i << 4) + (lane >> 2);
            const int c0 = tn + (j << 3) + ((lane & 3) << 1);
            tile[r0 * 264 + c0]           = acc[i][j][0];
            tile[r0 * 264 + c0 + 1]       = acc[i][j][1];
            tile[(r0 + 8) * 264 + c0]     = acc[i][j][2];
            tile[(r0 + 8) * 264 + c0 + 1] = acc[i][j][3];
        }
    __syncthreads();

    for (int rr = 0; rr < 16; ++rr) {
        const int row = warp * 16 + rr;
        const int grow = bm * 128 + row;
        const float* tr = tile + row * 264;
        const int pos = grow & (S_LEN - 1);
        const float c = fc[pos * 32 + lane];
        const float sn = fs[pos * 32 + lane];

        #pragma unroll
        for (int h = 0; h < 2; ++h) {
            if (PROJ && h == 1) {
                wout[(size_t)grow * 64 + lane]      = tr[128 + lane];
                wout[(size_t)grow * 64 + lane + 32] = tr[160 + lane];
                break;
            }
            float v0 = tr[h*128 + lane],      v1 = tr[h*128 + lane + 32];
            float v2 = tr[h*128 + lane + 64], v3 = tr[h*128 + lane + 96];

            if (PROJ) {
                float sum = v0 + v1 + v2 + v3;
                float sq  = v0*v0 + v1*v1 + v2*v2 + v3*v3;
                #pragma unroll
                for (int o = 16; o; o >>= 1) {
                    sum += __shfl_xor_sync(0xffffffffu, sum, o);
                    sq  += __shfl_xor_sync(0xffffffffu, sq,  o);
                }
                const float mu  = sum * (1.f / 128.f);
                const float var = sq * (1.f / 128.f) - mu * mu;
                const float r   = rsqrtf(var + 1e-5f);
                v0 = (v0 - mu) * r * kg[lane]      + kb[lane];
                v1 = (v1 - mu) * r * kg[lane + 32] + kb[lane + 32];
                v2 = (v2 - mu) * r * kg[lane + 64] + kb[lane + 64];
                v3 = (v3 - mu) * r * kg[lane + 96] + kb[lane + 96];
            }

            const float x1 = v0, x2 = v1;
            v0 = x1 * c - x2 * sn;
            v1 = x1 * sn + x2 * c;

            #pragma unroll
            for (int st = 1; st < 32; st <<= 1) {
                float p0 = __shfl_xor_sync(0xffffffffu, v0, st);
                float p1 = __shfl_xor_sync(0xffffffffu, v1, st);
                float p2 = __shfl_xor_sync(0xffffffffu, v2, st);
                float p3 = __shfl_xor_sync(0xffffffffu, v3, st);
                if (lane & st) { v0 = p0 - v0; v1 = p1 - v1; v2 = p2 - v2; v3 = p3 - v3; }
                else           { v0 += p0;     v1 += p1;     v2 += p2;     v3 += p3;     }
            }
            float t0 = v0 + v1, t1 = v0 - v1, t2 = v2 + v3, t3 = v2 - v3;
            v0 = t0 + t2; v2 = t0 - t2; v1 = t1 + t3; v3 = t1 - t3;

            if (PROJ) {
                float* ob = kout + (size_t)grow * 128;
                ob[lane]      = v0 * HSCALE;
                ob[lane + 32] = v1 * HSCALE;
                ob[lane + 64] = v2 * HSCALE;
                ob[lane + 96] = v3 * HSCALE;
            } else {
                float* ob = qout + (size_t)grow * 8192 + bn * 256 + h * 128;
                ob[lane]      = v0 * HSCALE;
                ob[lane + 32] = v1 * HSCALE;
                ob[lane + 64] = v2 * HSCALE;
                ob[lane + 96] = v3 * HSCALE;
            }
        }
    }
}

__global__ void write_end(float* __restrict__ eout, const int* __restrict__ sp)
{
    *eout = (float)(*sp + S_LEN);
}

// =====================================================================
typedef CUresult (*EncodeFn)(CUtensorMap*, CUtensorMapDataType, cuuint32_t, void*,
                             const cuuint64_t*, const cuuint64_t*, const cuuint32_t*,
                             const cuuint32_t*, CUtensorMapInterleave, CUtensorMapSwizzle,
                             CUtensorMapL2promotion, CUtensorMapFloatOOBfill);

static void make_map(EncodeFn enc, CUtensorMap* m, void* base, int K, int R, int boxR)
{
    cuuint64_t dims[3]    = {(cuuint64_t)K, (cuuint64_t)R, 1};
    cuuint64_t strides[2] = {(cuuint64_t)K * 2, (cuuint64_t)K * 2 * (cuuint64_t)R};
    cuuint32_t box[3]     = {64, (cuuint32_t)boxR, 1};
    cuuint32_t es[3]      = {1, 1, 1};
    enc(m, CU_TENSOR_MAP_DATA_TYPE_BFLOAT16, 3, base, dims, strides, box, es,
        CU_TENSOR_MAP_INTERLEAVE_NONE, CU_TENSOR_MAP_SWIZZLE_128B,
        CU_TENSOR_MAP_L2_PROMOTION_L2_128B, CU_TENSOR_MAP_FLOAT_OOB_FILL_NONE);
}

extern "C" void kernel_launch(void* const* d_in, const int* in_sizes, int n_in,
                              void* d_out, int out_size)
{
    const float* x   = (const float*)d_in[0];
    const float* qr  = (const float*)d_in[1];
    const float* fc  = (const float*)d_in[2];
    const float* fs  = (const float*)d_in[3];
    const float* wqb = (const float*)d_in[4];
    const float* wk  = (const float*)d_in[5];
    const float* kg  = (const float*)d_in[6];
    const float* kb  = (const float*)d_in[7];
    const float* wp  = (const float*)d_in[8];
    const int*   sp  = (const int*)d_in[9];

    float* out  = (float*)d_out;
    float* qout = out;
    float* wout = out + QN;
    float* kout = out + QN + WN;
    float* eout = out + QN + WN + KN;

    void *qrh, *qrl, *wqh, *wql, *xh, *xl, *wbh, *wbl;
    cudaGetSymbolAddress(&qrh, g_qr_h);
    cudaGetSymbolAddress(&qrl, g_qr_l);
    cudaGetSymbolAddress(&wqh, g_wq_h);
    cudaGetSymbolAddress(&wql, g_wq_l);
    cudaGetSymbolAddress(&xh,  g_x_h);
    cudaGetSymbolAddress(&xl,  g_x_l);
    cudaGetSymbolAddress(&wbh, g_wb_h);
    cudaGetSymbolAddress(&wbl, g_wb_l);

    EncodeFn enc = nullptr;
    cudaDriverEntryPointQueryResult qres;
    cudaGetDriverEntryPoint("cuTensorMapEncodeTiled", (void**)&enc, cudaEnableDefault, &qres);

    CUtensorMap mQAh, mQAl, mQBh, mQBl, mPAh, mPAl, mPBh, mPBl;
    make_map(enc, &mQAh, qrh, LORA, NROWS, 128);
    make_map(enc, &mQAl, qrl, LORA, NROWS, 128);
    make_map(enc, &mQBh, wqh, LORA, NROWS, 256);
    make_map(enc, &mQBl, wql, LORA, NROWS, 256);
    make_map(enc, &mPAh, xh,  D_IN, NROWS, 128);
    make_map(enc, &mPAl, xl,  D_IN, NROWS, 128);
    make_map(enc, &mPBh, wbh, D_IN, 256, 256);
    make_map(enc, &mPBl, wbl, D_IN, 256, 256);

    cudaFuncSetAttribute(fused_gemm<false>, cudaFuncAttributeMaxDynamicSharedMemorySize, SMEM_TOT);
    cudaFuncSetAttribute(fused_gemm<true>,  cudaFuncAttributeMaxDynamicSharedMemorySize, SMEM_TOT);

    // ---- static streams / events (created once, on the first eager call) ----
    static cudaStream_t sHi = nullptr;   // high priority: prep_q, gemm_proj
    static cudaStream_t sLo = nullptr;   // default priority: prep_x
    static cudaEvent_t evFork = nullptr, evPq = nullptr, evPx = nullptr,
                       evJ1 = nullptr, evJ2 = nullptr;
    if (!sHi) {
        int plo, phi;
        cudaDeviceGetStreamPriorityRange(&plo, &phi);
        cudaStreamCreateWithPriority(&sHi, cudaStreamNonBlocking, phi);
        cudaStreamCreateWithPriority(&sLo, cudaStreamNonBlocking, plo);
        cudaEventCreateWithFlags(&evFork, cudaEventDisableTiming);
        cudaEventCreateWithFlags(&evPq,   cudaEventDisableTiming);
        cudaEventCreateWithFlags(&evPx,   cudaEventDisableTiming);
        cudaEventCreateWithFlags(&evJ1,   cudaEventDisableTiming);
        cudaEventCreateWithFlags(&evJ2,   cudaEventDisableTiming);
    }

    // fork from the (possibly capturing) legacy stream
    cudaEventRecord(evFork, 0);
    cudaStreamWaitEvent(sHi, evFork, 0);
    cudaStreamWaitEvent(sLo, evFork, 0);

    // chain 1: prep_q (high pri, runs first) -> gemm_q (legacy stream, default pri)
    prep_q<<<(PREPQ_TOTAL + 255) / 256, 256, 0, sHi>>>(
        (const float4*)qr, (const float4*)wqb, wk, wp);
    cudaEventRecord(evPq, sHi);
    cudaStreamWaitEvent(0, evPq, 0);
    fused_gemm<false><<<2048, 256, SMEM_TOT, 0>>>(
        mQAh, mQAl, mQBh, mQBl, qout, kout, wout, fc, fs, kg, kb);

    // chain 2: prep_x (low pri, overlaps gemm_q) -> gemm_proj (high pri)
    prep_x<<<(N4X + 255) / 256, 256, 0, sLo>>>((const float4*)x);
    cudaEventRecord(evPx, sLo);
    cudaStreamWaitEvent(sHi, evPx, 0);
    fused_gemm<true><<<64, 256, SMEM_TOT, sHi>>>(
        mPAh, mPAl, mPBh, mPBl, qout, kout, wout, fc, fs, kg, kb);

    // join both side streams back into the legacy stream
    cudaEventRecord(evJ1, sHi);
    cudaStreamWaitEvent(0, evJ1, 0);
    cudaEventRecord(evJ2, sLo);
    cudaStreamWaitEvent(0, evJ2, 0);

    write_end<<<1, 1, 0, 0>>>(eout, sp);
}

// round 10
// speedup vs baseline: 1.1054x; 1.1054x over previous
#include <cuda_runtime.h>
#include <cuda_bf16.h>
#include <cuda.h>
#include <cstdint>

// ---------------- problem constants ----------------
#define S_LEN 4096
#define NROWS 8192
#define D_IN  7168
#define LORA  1536
#define NH    64
#define DHD   128
#define QN    (NROWS * NH * DHD)
#define WN    (NROWS * NH)
#define KN    (NROWS * DHD)

#define WSCALE 0.011048543456039806f  // (H*DH)^-0.5
#define HSCALE 0.08838834764831845f   // 128^-0.5

// grid layout: 2112 blocks = 2048 q + 64 proj; proj occupies [1344,1408)
#define NPROJ    64
#define PROJ_POS 1344
#define GRID_TOT 2112

// ---------------- device scratch (bf16 hi/lo splits) ----------------
__device__ __nv_bfloat16 g_qr_h[NROWS * LORA];
__device__ __nv_bfloat16 g_qr_l[NROWS * LORA];
__device__ __nv_bfloat16 g_wq_h[NROWS * LORA];
__device__ __nv_bfloat16 g_wq_l[NROWS * LORA];
__device__ __nv_bfloat16 g_x_h[(size_t)NROWS * D_IN];
__device__ __nv_bfloat16 g_x_l[(size_t)NROWS * D_IN];
__device__ __nv_bfloat16 g_wb_h[256 * D_IN];
__device__ __nv_bfloat16 g_wb_l[256 * D_IN];
__device__ unsigned int  g_xdone;      // prep_x completion counter

// ---------------- split helpers ----------------
__device__ __forceinline__ uint32_t pack_bf2(__nv_bfloat16 a, __nv_bfloat16 b) {
    return (uint32_t)__bfloat16_as_ushort(a) | ((uint32_t)__bfloat16_as_ushort(b) << 16);
}
__device__ __forceinline__ void split4(float4 v, uint2& hi, uint2& lo) {
    __nv_bfloat16 hx = __float2bfloat16_rn(v.x);
    __nv_bfloat16 hy = __float2bfloat16_rn(v.y);
    __nv_bfloat16 hz = __float2bfloat16_rn(v.z);
    __nv_bfloat16 hw = __float2bfloat16_rn(v.w);
    __nv_bfloat16 lx = __float2bfloat16_rn(v.x - __bfloat162float(hx));
    __nv_bfloat16 ly = __float2bfloat16_rn(v.y - __bfloat162float(hy));
    __nv_bfloat16 lz = __float2bfloat16_rn(v.z - __bfloat162float(hz));
    __nv_bfloat16 lw = __float2bfloat16_rn(v.w - __bfloat162float(hw));
    hi = make_uint2(pack_bf2(hx, hy), pack_bf2(hz, hw));
    lo = make_uint2(pack_bf2(lx, ly), pack_bf2(lz, lw));
}

#define N4Q (NROWS * LORA / 4)
#define N4X (NROWS * D_IN / 4)
#define N4B (256 * D_IN / 4)
#define PREPQ_TOTAL (2 * N4Q + N4B)
#define XBLOCKS (N4X / 256)            // 57344, exact

// prep for the q chain + proj weights (small, gates the GEMM launch)
__global__ void prep_q(const float4* __restrict__ qr, const float4* __restrict__ wqb,
                       const float* __restrict__ wk, const float* __restrict__ wp)
{
    int i = blockIdx.x * blockDim.x + threadIdx.x;
    if (i >= PREPQ_TOTAL) return;
    if (i < N4Q) {
        uint2 h, l; split4(qr[i], h, l);
        ((uint2*)g_qr_h)[i] = h; ((uint2*)g_qr_l)[i] = l;
    } else if (i < 2 * N4Q) {
        int j = i - N4Q;
        uint2 h, l; split4(wqb[j], h, l);
        ((uint2*)g_wq_h)[j] = h; ((uint2*)g_wq_l)[j] = l;
    } else {
        int j = i - 2 * N4Q;
        int row = j / (D_IN / 4);
        int c4  = j % (D_IN / 4);
        float4 v;
        if (row < 128)      v = ((const float4*)wk)[row * (D_IN / 4) + c4];
        else if (row < 192) {
            v = ((const float4*)wp)[(row - 128) * (D_IN / 4) + c4];
            v.x *= WSCALE; v.y *= WSCALE; v.z *= WSCALE; v.w *= WSCALE;
        } else v = make_float4(0.f, 0.f, 0.f, 0.f);
        uint2 h, l; split4(v, h, l);
        ((uint2*)g_wb_h)[j] = h; ((uint2*)g_wb_l)[j] = l;
    }
}

__global__ void reset_flag() { g_xdone = 0u; }

// x splits; signals completion via counter (proj blocks gate on it)
__global__ void prep_x(const float4* __restrict__ x)
{
    int i = blockIdx.x * blockDim.x + threadIdx.x;
    uint2 h, l; split4(x[i], h, l);
    ((uint2*)g_x_h)[i] = h; ((uint2*)g_x_l)[i] = l;
    __syncthreads();
    if (threadIdx.x == 0) {
        __threadfence();
        atomicAdd(&g_xdone, 1u);
    }
}

// ---------------- PTX helpers ----------------
__device__ __forceinline__ uint32_t elect_one_pred() {
    uint32_t p;
    asm volatile("{\n\t.reg .pred p;\n\telect.sync _|p, 0xFFFFFFFF;\n\tselp.b32 %0, 1, 0, p;\n\t}" : "=r"(p));
    return p;
}
__device__ __forceinline__ uint32_t smem_u32(const void* p) {
    uint32_t a;
    asm("{ .reg .u64 t; cvta.to.shared.u64 t, %1; cvt.u32.u64 %0, t; }" : "=r"(a) : "l"(p));
    return a;
}

#define MBARRIER_INIT(a, c) \
    asm volatile("mbarrier.init.shared.b64 [%0], %1;" :: "r"((uint32_t)(a)), "r"((uint32_t)(c)) : "memory")
#define MBARRIER_EXPECT_TX(a, b) \
    asm volatile("mbarrier.arrive.expect_tx.shared.b64 _, [%0], %1;" :: "r"((uint32_t)(a)), "r"((uint32_t)(b)) : "memory")
#define MBARRIER_ARRIVE(a) \
    asm volatile("mbarrier.arrive.shared.b64 _, [%0];" :: "r"((uint32_t)(a)) : "memory")

#define MBARRIER_WAIT_PARITY(mbar, par) do {                                          \
    uint32_t _m = (uint32_t)(mbar), _p = (uint32_t)(par), _d;                         \
    asm volatile("{\n\t.reg .pred p;\n\t"                                             \
        "mbarrier.try_wait.parity.acquire.cta.shared::cta.b64 p, [%1], %2;\n\t"       \
        "selp.b32 %0, 1, 0, p;\n\t}" : "=r"(_d) : "r"(_m), "r"(_p) : "memory");       \
    if (!_d) {                                                                         \
        asm volatile("{\n\t.reg .pred P1;\n\t"                                        \
            "WL_%=:\n\t"                                                              \
            "mbarrier.try_wait.parity.acquire.cta.shared::cta.b64 P1, [%0], %1, 0x989680;\n\t" \
            "@P1 bra.uni WD_%=;\n\t"                                                  \
            "bra.uni WL_%=;\n\t"                                                      \
            "WD_%=:\n\t}" :: "r"(_m), "r"(_p) : "memory");                            \
    }                                                                                  \
} while (0)

#define MBARRIER_WAIT_PARITY_RELAXED(mbar, par) do {                                  \
    uint32_t _m = (uint32_t)(mbar), _p = (uint32_t)(par), _d;                         \
    asm volatile("{\n\t.reg .pred p;\n\t"                                             \
        "mbarrier.try_wait.parity.relaxed.cta.shared::cta.b64 p, [%1], %2, 0x989680;\n\t" \
        "selp.b32 %0, 1, 0, p;\n\t}" : "=r"(_d) : "r"(_m), "r"(_p) : "memory");       \
    if (!_d) {                                                                         \
        asm volatile("{\n\t.reg .pred P1;\n\t"                                        \
            "WL_%=:\n\t"                                                              \
            "mbarrier.try_wait.parity.relaxed.cta.shared::cta.b64 P1, [%0], %1, 0x989680;\n\t" \
            "@P1 bra.uni WD_%=;\n\t"                                                  \
            "bra.uni WL_%=;\n\t"                                                      \
            "WD_%=:\n\t}" :: "r"(_m), "r"(_p) : "memory");                            \
    }                                                                                  \
} while (0)

#define TMA_LOAD_3D(sa, tm, cx, cy, cz, mb)                                           \
    asm volatile("cp.async.bulk.tensor.3d.shared::cta.global.tile.mbarrier::complete_tx::bytes " \
        "[%0], [%1, {%2, %3, %4}], [%5];"                                             \
        :: "r"((uint32_t)(sa)), "l"(tm), "r"((int)(cx)), "r"((int)(cy)), "r"((int)(cz)), \
           "r"((uint32_t)(mb)) : "memory")

#define FENCE_PROXY_ASYNC() asm volatile("fence.proxy.async.shared::cta;" ::: "memory")

#define LDSM4(r0, r1, r2, r3, addr)                                              \
    asm volatile("ldmatrix.sync.aligned.m8n8.x4.shared.b16 {%0,%1,%2,%3},[%4];"  \
                 : "=r"(r0), "=r"(r1), "=r"(r2), "=r"(r3) : "r"(addr))

#define MMA_BF16(d, a, b)                                                        \
    asm volatile("mma.sync.aligned.m16n8k16.row.col.f32.bf16.bf16.f32 "          \
                 "{%0,%1,%2,%3},{%4,%5,%6,%7},{%8,%9},{%0,%1,%2,%3};"            \
                 : "+f"((d)[0]), "+f"((d)[1]), "+f"((d)[2]), "+f"((d)[3])        \
                 : "r"((a)[0]), "r"((a)[1]), "r"((a)[2]), "r"((a)[3]),           \
                   "r"((b)[0]), "r"((b)[1]))

// SW128 swizzle: XOR bits [9:7] into bits [6:4] (128B rows)
__device__ __forceinline__ uint32_t swz(uint32_t o) { return o ^ ((o >> 3) & 0x70); }

// ---------------- smem layout ----------------
#define CTRL     1024
#define STAGE_B  98304
#define AH_O     0
#define AL_O     16384
#define BH_O     32768
#define BL_O     65536
#define NSTAGE   2
#define SMEM_TOT (CTRL + NSTAGE * STAGE_B)   // 197632 -> 1 CTA/SM

// =====================================================================
// Unified TMA-fed mma.sync GEMM, tile 128x256, fused epilogues.
// q blocks first; 64 proj blocks mid-grid, gated on prep_x flag.
// =====================================================================
__global__ __launch_bounds__(256, 1)
void fused_gemm(const __grid_constant__ CUtensorMap mQAh, const __grid_constant__ CUtensorMap mQAl,
                const __grid_constant__ CUtensorMap mQBh, const __grid_constant__ CUtensorMap mQBl,
                const __grid_constant__ CUtensorMap mPAh, const __grid_constant__ CUtensorMap mPAl,
                const __grid_constant__ CUtensorMap mPBh, const __grid_constant__ CUtensorMap mPBl,
                float* __restrict__ qout, float* __restrict__ kout, float* __restrict__ wout,
                const float* __restrict__ fc, const float* __restrict__ fs,
                const float* __restrict__ kg, const float* __restrict__ kb)
{
    extern __shared__ char smem_raw[];
    const uint32_t sb = smem_u32(smem_raw);
    const int tid = threadIdx.x, lane = tid & 31, warp = tid >> 5;
    const int wm = warp >> 2, wn = warp & 3;
    const int tm = wm << 6, tn = wn << 6;     // warp tile 64x64

    const int bid = blockIdx.x;
    const bool proj = (bid >= PROJ_POS) && (bid < PROJ_POS + NPROJ);
    int bm, bn, K;
    const CUtensorMap *pAh, *pAl, *pBh, *pBl;
    if (proj) {
        bm = bid - PROJ_POS; bn = 0; K = D_IN;
        pAh = &mPAh; pAl = &mPAl; pBh = &mPBh; pBl = &mPBl;
    } else {
        const int t = bid - (bid >= PROJ_POS + NPROJ ? NPROJ : 0);
        bm = t & 63; bn = t >> 6; K = LORA;
        pAh = &mQAh; pAl = &mQAl; pBh = &mQBh; pBl = &mQBl;
    }
    const int niter = K >> 6;

    if (tid == 0) {
        MBARRIER_INIT(sb + 0, 1);
        MBARRIER_INIT(sb + 8, 1);
        MBARRIER_INIT(sb + 16, 8);
        MBARRIER_INIT(sb + 24, 8);
        FENCE_PROXY_ASYNC();
    }
    __syncthreads();

    const bool producer = (warp == 0) && elect_one_pred();
    const bool wleader  = elect_one_pred();

    if (producer) {
        if (proj) {
            // gate on prep_x completion (usually long done by the time we run)
            while (atomicAdd(&g_xdone, 0u) != (unsigned)XBLOCKS) __nanosleep(256);
            asm volatile("fence.proxy.async;" ::: "memory");
        }
        #pragma unroll
        for (int p = 0; p < NSTAGE; ++p) {
            const uint32_t fb = sb + p * 8;
            MBARRIER_EXPECT_TX(fb, STAGE_B);
            const uint32_t tb = sb + CTRL + p * STAGE_B;
            const int kt = p << 6;
            TMA_LOAD_3D(tb + AH_O, pAh, kt, bm * 128, 0, fb);
            TMA_LOAD_3D(tb + AL_O, pAl, kt, bm * 128, 0, fb);
            TMA_LOAD_3D(tb + BH_O, pBh, kt, bn * 256, 0, fb);
            TMA_LOAD_3D(tb + BL_O, pBl, kt, bn * 256, 0, fb);
        }
    }

    float acc[4][8][4] = {};
    int fph[NSTAGE] = {0, 0};
    int eph[NSTAGE] = {0, 0};

    int s = 0;
    for (int it = 0; it < niter; ++it) {
        MBARRIER_WAIT_PARITY(sb + s * 8, fph[s]);
        fph[s] ^= 1;
        const uint32_t tb = sb + CTRL + s * STAGE_B;

        #pragma unroll
        for (int s2 = 0; s2 < 4; ++s2) {
            const uint32_t kbyte = s2 << 5;
            uint32_t bhf[8][2], blf[8][2];
            {
                const int g = lane >> 3;
                #pragma unroll
                for (int p = 0; p < 4; ++p) {
                    const int row = tn + (((p << 1) + (g >> 1)) << 3) + (lane & 7);
                    const uint32_t off = swz(row * 128 + kbyte + ((g & 1) << 4));
                    LDSM4(bhf[2*p][0], bhf[2*p][1], bhf[2*p+1][0], bhf[2*p+1][1], tb + BH_O + off);
                    LDSM4(blf[2*p][0], blf[2*p][1], blf[2*p+1][0], blf[2*p+1][1], tb + BL_O + off);
                }
            }
            uint32_t a[4][4];
            #pragma unroll
            for (int i = 0; i < 4; ++i) {
                const int row = tm + (i << 4) + (lane & 15);
                const uint32_t off = swz(row * 128 + kbyte + ((lane >> 4) << 4));
                LDSM4(a[i][0], a[i][1], a[i][2], a[i][3], tb + AH_O + off);
            }
            #pragma unroll
            for (int i = 0; i < 4; ++i)
                #pragma unroll
                for (int j = 0; j < 8; ++j) {
                    MMA_BF16(acc[i][j], a[i], bhf[j]);
                    MMA_BF16(acc[i][j], a[i], blf[j]);
                }
            #pragma unroll
            for (int i = 0; i < 4; ++i) {
                const int row = tm + (i << 4) + (lane & 15);
                const uint32_t off = swz(row * 128 + kbyte + ((lane >> 4) << 4));
                LDSM4(a[i][0], a[i][1], a[i][2], a[i][3], tb + AL_O + off);
            }
            #pragma unroll
            for (int i = 0; i < 4; ++i)
                #pragma unroll
                for (int j = 0; j < 8; ++j)
                    MMA_BF16(acc[i][j], a[i], bhf[j]);
        }

        if (wleader) MBARRIER_ARRIVE(sb + 16 + s * 8);

        if (producer && it + NSTAGE < niter) {
            MBARRIER_WAIT_PARITY_RELAXED(sb + 16 + s * 8, eph[s]);
            eph[s] ^= 1;
            const uint32_t fb = sb + s * 8;
            MBARRIER_EXPECT_TX(fb, STAGE_B);
            const int kt = (it + NSTAGE) << 6;
            TMA_LOAD_3D(tb + AH_O, pAh, kt, bm * 128, 0, fb);
            TMA_LOAD_3D(tb + AL_O, pAl, kt, bm * 128, 0, fb);
            TMA_LOAD_3D(tb + BH_O, pBh, kt, bn * 256, 0, fb);
            TMA_LOAD_3D(tb + BL_O, pBl, kt, bn * 256, 0, fb);
        }
        if (++s == NSTAGE) s = 0;
    }

    // ================= fused epilogue =================
    __syncthreads();
    float* tile = reinterpret_cast<float*>(smem_raw + CTRL);   // [128][264]
    #pragma unroll
    for (int i = 0; i < 4; ++i)
        #pragma unroll
        for (int j = 0; j < 8; ++j) {
            const int r0 = tm + (i << 4) + (lane >> 2);
            const int c0 = tn + (j << 3) + ((lane & 3) << 1);
            tile[r0 * 264 + c0]           = acc[i][j][0];
            tile[r0 * 264 + c0 + 1]       = acc[i][j][1];
            tile[(r0 + 8) * 264 + c0]     = acc[i][j][2];
            tile[(r0 + 8) * 264 + c0 + 1] = acc[i][j][3];
        }
    __syncthreads();

    for (int rr = 0; rr < 16; ++rr) {
        const int row = warp * 16 + rr;
        const int grow = bm * 128 + row;
        const float* tr = tile + row * 264;
        const int pos = grow & (S_LEN - 1);
        const float c = fc[pos * 32 + lane];
        const float sn = fs[pos * 32 + lane];

        #pragma unroll
        for (int h = 0; h < 2; ++h) {
            if (proj && h == 1) {
                wout[(size_t)grow * 64 + lane]      = tr[128 + lane];
                wout[(size_t)grow * 64 + lane + 32] = tr[160 + lane];
                break;
            }
            float v0 = tr[h*128 + lane],      v1 = tr[h*128 + lane + 32];
            float v2 = tr[h*128 + lane + 64], v3 = tr[h*128 + lane + 96];

            if (proj) {
                float sum = v0 + v1 + v2 + v3;
                float sq  = v0*v0 + v1*v1 + v2*v2 + v3*v3;
                #pragma unroll
                for (int o = 16; o; o >>= 1) {
                    sum += __shfl_xor_sync(0xffffffffu, sum, o);
                    sq  += __shfl_xor_sync(0xffffffffu, sq,  o);
                }
                const float mu  = sum * (1.f / 128.f);
                const float var = sq * (1.f / 128.f) - mu * mu;
                const float r   = rsqrtf(var + 1e-5f);
                v0 = (v0 - mu) * r * kg[lane]      + kb[lane];
                v1 = (v1 - mu) * r * kg[lane + 32] + kb[lane + 32];
                v2 = (v2 - mu) * r * kg[lane + 64] + kb[lane + 64];
                v3 = (v3 - mu) * r * kg[lane + 96] + kb[lane + 96];
            }

            const float x1 = v0, x2 = v1;
            v0 = x1 * c - x2 * sn;
            v1 = x1 * sn + x2 * c;

            #pragma unroll
            for (int st = 1; st < 32; st <<= 1) {
                float p0 = __shfl_xor_sync(0xffffffffu, v0, st);
                float p1 = __shfl_xor_sync(0xffffffffu, v1, st);
                float p2 = __shfl_xor_sync(0xffffffffu, v2, st);
                float p3 = __shfl_xor_sync(0xffffffffu, v3, st);
                if (lane & st) { v0 = p0 - v0; v1 = p1 - v1; v2 = p2 - v2; v3 = p3 - v3; }
                else           { v0 += p0;     v1 += p1;     v2 += p2;     v3 += p3;     }
            }
            float t0 = v0 + v1, t1 = v0 - v1, t2 = v2 + v3, t3 = v2 - v3;
            v0 = t0 + t2; v2 = t0 - t2; v1 = t1 + t3; v3 = t1 - t3;

            if (proj) {
                float* ob = kout + (size_t)grow * 128;
                ob[lane]      = v0 * HSCALE;
                ob[lane + 32] = v1 * HSCALE;
                ob[lane + 64] = v2 * HSCALE;
                ob[lane + 96] = v3 * HSCALE;
            } else {
                float* ob = qout + (size_t)grow * 8192 + bn * 256 + h * 128;
                ob[lane]      = v0 * HSCALE;
                ob[lane + 32] = v1 * HSCALE;
                ob[lane + 64] = v2 * HSCALE;
                ob[lane + 96] = v3 * HSCALE;
            }
        }
    }
}

__global__ void write_end(float* __restrict__ eout, const int* __restrict__ sp)
{
    *eout = (float)(*sp + S_LEN);
}

// =====================================================================
typedef CUresult (*EncodeFn)(CUtensorMap*, CUtensorMapDataType, cuuint32_t, void*,
                             const cuuint64_t*, const cuuint64_t*, const cuuint32_t*,
                             const cuuint32_t*, CUtensorMapInterleave, CUtensorMapSwizzle,
                             CUtensorMapL2promotion, CUtensorMapFloatOOBfill);

static void make_map(EncodeFn enc, CUtensorMap* m, void* base, int K, int R, int boxR)
{
    cuuint64_t dims[3]    = {(cuuint64_t)K, (cuuint64_t)R, 1};
    cuuint64_t strides[2] = {(cuuint64_t)K * 2, (cuuint64_t)K * 2 * (cuuint64_t)R};
    cuuint32_t box[3]     = {64, (cuuint32_t)boxR, 1};
    cuuint32_t es[3]      = {1, 1, 1};
    enc(m, CU_TENSOR_MAP_DATA_TYPE_BFLOAT16, 3, base, dims, strides, box, es,
        CU_TENSOR_MAP_INTERLEAVE_NONE, CU_TENSOR_MAP_SWIZZLE_128B,
        CU_TENSOR_MAP_L2_PROMOTION_L2_128B, CU_TENSOR_MAP_FLOAT_OOB_FILL_NONE);
}

extern "C" void kernel_launch(void* const* d_in, const int* in_sizes, int n_in,
                              void* d_out, int out_size)
{
    const float* x   = (const float*)d_in[0];
    const float* qr  = (const float*)d_in[1];
    const float* fc  = (const float*)d_in[2];
    const float* fs  = (const float*)d_in[3];
    const float* wqb = (const float*)d_in[4];
    const float* wk  = (const float*)d_in[5];
    const float* kg  = (const float*)d_in[6];
    const float* kb  = (const float*)d_in[7];
    const float* wp  = (const float*)d_in[8];
    const int*   sp  = (const int*)d_in[9];

    float* out  = (float*)d_out;
    float* qout = out;
    float* wout = out + QN;
    float* kout = out + QN + WN;
    float* eout = out + QN + WN + KN;

    void *qrh, *qrl, *wqh, *wql, *xh, *xl, *wbh, *wbl;
    cudaGetSymbolAddress(&qrh, g_qr_h);
    cudaGetSymbolAddress(&qrl, g_qr_l);
    cudaGetSymbolAddress(&wqh, g_wq_h);
    cudaGetSymbolAddress(&wql, g_wq_l);
    cudaGetSymbolAddress(&xh,  g_x_h);
    cudaGetSymbolAddress(&xl,  g_x_l);
    cudaGetSymbolAddress(&wbh, g_wb_h);
    cudaGetSymbolAddress(&wbl, g_wb_l);

    EncodeFn enc = nullptr;
    cudaDriverEntryPointQueryResult qres;
    cudaGetDriverEntryPoint("cuTensorMapEncodeTiled", (void**)&enc, cudaEnableDefault, &qres);

    CUtensorMap mQAh, mQAl, mQBh, mQBl, mPAh, mPAl, mPBh, mPBl;
    make_map(enc, &mQAh, qrh, LORA, NROWS, 128);
    make_map(enc, &mQAl, qrl, LORA, NROWS, 128);
    make_map(enc, &mQBh, wqh, LORA, NROWS, 256);
    make_map(enc, &mQBl, wql, LORA, NROWS, 256);
    make_map(enc, &mPAh, xh,  D_IN, NROWS, 128);
    make_map(enc, &mPAl, xl,  D_IN, NROWS, 128);
    make_map(enc, &mPBh, wbh, D_IN, 256, 256);
    make_map(enc, &mPBl, wbl, D_IN, 256, 256);

    cudaFuncSetAttribute(fused_gemm, cudaFuncAttributeMaxDynamicSharedMemorySize, SMEM_TOT);

    // ---- static streams / events (created once) ----
    static cudaStream_t sA = nullptr;   // high pri: prep_q
    static cudaStream_t sB = nullptr;   // high pri: reset + prep_x
    static cudaEvent_t evFork = nullptr, evPq = nullptr, evJB = nullptr;
    if (!sA) {
        int plo, phi;
        cudaDeviceGetStreamPriorityRange(&plo, &phi);
        cudaStreamCreateWithPriority(&sA, cudaStreamNonBlocking, phi);
        cudaStreamCreateWithPriority(&sB, cudaStreamNonBlocking, phi);
        cudaEventCreateWithFlags(&evFork, cudaEventDisableTiming);
        cudaEventCreateWithFlags(&evPq,   cudaEventDisableTiming);
        cudaEventCreateWithFlags(&evJB,   cudaEventDisableTiming);
    }

    // fork from the legacy stream
    cudaEventRecord(evFork, 0);
    cudaStreamWaitEvent(sA, evFork, 0);
    cudaStreamWaitEvent(sB, evFork, 0);

    // both preps at high priority, concurrent
    prep_q<<<(PREPQ_TOTAL + 255) / 256, 256, 0, sA>>>(
        (const float4*)qr, (const float4*)wqb, wk, wp);
    cudaEventRecord(evPq, sA);

    reset_flag<<<1, 1, 0, sB>>>();
    prep_x<<<XBLOCKS, 256, 0, sB>>>((const float4*)x);

    // GEMM waits only on prep_q; proj blocks gate on the prep_x flag in-kernel
    cudaStreamWaitEvent(0, evPq, 0);
    fused_gemm<<<GRID_TOT, 256, SMEM_TOT, 0>>>(
        mQAh, mQAl, mQBh, mQBl, mPAh, mPAl, mPBh, mPBl,
        qout, kout, wout, fc, fs, kg, kb);

    // join prep_x stream before graph end
    cudaEventRecord(evJB, sB);
    cudaStreamWaitEvent(0, evJB, 0);
    write_end<<<1, 1, 0, 0>>>(eout, sp);
}